// round 1
// baseline (speedup 1.0000x reference)
#include <cuda_runtime.h>
#include <cuda_bf16.h>

#define N_NODES  100000
#define N_EDGES  1600000
#define N_GRAPHS 100
#define SCAN_B   1024
#define NB_SCAN  ((N_NODES + SCAN_B - 1) / SCAN_B)   // 98

// ---------------- scratch (static __device__ allocations only) ----------------
__device__ float g_h1[N_NODES * 128];
__device__ float g_h2[N_NODES * 118];
__device__ float g_h3[N_NODES * 103];
__device__ float g_h4[N_NODES * 5];
__device__ float g_agg[N_NODES * 128];
__device__ float g_invdeg[N_NODES];
__device__ int   g_rowcnt[N_NODES];
__device__ int   g_rowptr[N_NODES];
__device__ int   g_cursor[N_NODES];
__device__ int   g_csr[N_EDGES];
__device__ int   g_bsum[128];
__device__ int   g_boff[128];
__device__ float g_pool[N_GRAPHS * 5];
__device__ int   g_gcnt[N_GRAPHS];

// ---------------- CSR build ----------------
__global__ void k_zero() {
    int i = blockIdx.x * blockDim.x + threadIdx.x;
    if (i < N_NODES) { g_rowcnt[i] = 0; g_cursor[i] = 0; }
    if (i < N_GRAPHS * 5) g_pool[i] = 0.f;
    if (i < N_GRAPHS) g_gcnt[i] = 0;
}

__global__ void k_count(const int* __restrict__ dst) {
    int e = blockIdx.x * blockDim.x + threadIdx.x;
    if (e < N_EDGES) atomicAdd(&g_rowcnt[dst[e]], 1);
}

__global__ void k_scan1() {
    __shared__ int s[SCAN_B];
    int tid = threadIdx.x;
    int gid = blockIdx.x * SCAN_B + tid;
    int v = (gid < N_NODES) ? g_rowcnt[gid] : 0;
    s[tid] = v;
    __syncthreads();
    for (int off = 1; off < SCAN_B; off <<= 1) {
        int t = (tid >= off) ? s[tid - off] : 0;
        __syncthreads();
        s[tid] += t;
        __syncthreads();
    }
    if (gid < N_NODES) g_rowptr[gid] = s[tid] - v;   // exclusive
    if (tid == SCAN_B - 1) g_bsum[blockIdx.x] = s[tid];
}

__global__ void k_scan2(int nb) {
    if (threadIdx.x == 0 && blockIdx.x == 0) {
        int run = 0;
        for (int b = 0; b < nb; ++b) { int t = g_bsum[b]; g_boff[b] = run; run += t; }
    }
}

__global__ void k_scan3() {
    int gid = blockIdx.x * SCAN_B + threadIdx.x;
    if (gid < N_NODES) g_rowptr[gid] += g_boff[blockIdx.x];
}

__global__ void k_invdeg() {
    int i = blockIdx.x * blockDim.x + threadIdx.x;
    if (i < N_NODES) {
        int c = g_rowcnt[i];
        g_invdeg[i] = 1.0f / (float)(c > 0 ? c : 1);
    }
}

__global__ void k_fill(const int* __restrict__ src, const int* __restrict__ dst) {
    int e = blockIdx.x * blockDim.x + threadIdx.x;
    if (e < N_EDGES) {
        int d = dst[e];
        int pos = atomicAdd(&g_cursor[d], 1);
        g_csr[g_rowptr[d] + pos] = src[e];
    }
}

// ---------------- neighbor mean aggregation (warp per node, no atomics) ----------------
__global__ void k_agg(const float* __restrict__ X, int din) {
    int warp = (int)((blockIdx.x * blockDim.x + threadIdx.x) >> 5);
    int lane = threadIdx.x & 31;
    if (warp >= N_NODES) return;
    int beg = g_rowptr[warp];
    int cnt = g_rowcnt[warp];
    int c0 = lane, c1 = lane + 32, c2 = lane + 64, c3 = lane + 96;
    bool b1 = c1 < din, b2 = c2 < din, b3 = c3 < din;
    float a0 = 0.f, a1 = 0.f, a2 = 0.f, a3 = 0.f;
    for (int j = 0; j < cnt; ++j) {
        int s = g_csr[beg + j];
        const float* row = X + (long)s * din;
        a0 += row[c0];
        if (b1) a1 += row[c1];
        if (b2) a2 += row[c2];
        if (b3) a3 += row[c3];
    }
    float inv = g_invdeg[warp];
    float* o = g_agg + (long)warp * din;
    o[c0] = a0 * inv;
    if (b1) o[c1] = a1 * inv;
    if (b2) o[c2] = a2 * inv;
    if (b3) o[c3] = a3 * inv;
}

// ---------------- fused SAGE GEMM: Y = relu?( X@Ws + Agg@Wn + b ) ----------------
// 128x128 tile, BK=8, 256 threads, 8x8 register tile per thread.
__global__ void __launch_bounds__(256, 2)
k_gemm(const float* __restrict__ X, const float* __restrict__ Ag,
       const float* __restrict__ Ws, const float* __restrict__ Wn,
       const float* __restrict__ bias, float* __restrict__ Y,
       int M, int K, int Nout, int do_relu)
{
    __shared__ float sA[8][132];   // pad 132: conflict-free STS for strided writes
    __shared__ float sB[8][132];
    int tid = threadIdx.x;
    int tx = tid & 15;         // 16 col groups
    int ty = tid >> 4;         // 16 row groups
    int m0 = blockIdx.y * 128;
    int n0 = blockIdx.x * 128;

    float acc[8][8];
    #pragma unroll
    for (int i = 0; i < 8; ++i)
        #pragma unroll
        for (int j = 0; j < 8; ++j) acc[i][j] = 0.f;

    for (int pass = 0; pass < 2; ++pass) {
        const float* A = pass ? Ag : X;
        const float* W = pass ? Wn : Ws;
        for (int k0 = 0; k0 < K; k0 += 8) {
            // A tile: 128 rows x 8 k
            #pragma unroll
            for (int i = 0; i < 4; ++i) {
                int idx = tid + i * 256;
                int r = idx >> 3, kk = idx & 7;
                int gr = m0 + r, gk = k0 + kk;
                sA[kk][r] = (gr < M && gk < K) ? A[(long)gr * K + gk] : 0.f;
            }
            // W tile: 8 k x 128 cols
            #pragma unroll
            for (int i = 0; i < 4; ++i) {
                int idx = tid + i * 256;
                int c = idx & 127, kk = idx >> 7;
                int gc = n0 + c, gk = k0 + kk;
                sB[kk][c] = (gk < K && gc < Nout) ? W[(long)gk * Nout + gc] : 0.f;
            }
            __syncthreads();
            #pragma unroll
            for (int kk = 0; kk < 8; ++kk) {
                float a[8], b[8];
                #pragma unroll
                for (int i = 0; i < 8; ++i) a[i] = sA[kk][ty * 8 + i];
                #pragma unroll
                for (int j = 0; j < 8; ++j) b[j] = sB[kk][tx * 8 + j];
                #pragma unroll
                for (int i = 0; i < 8; ++i)
                    #pragma unroll
                    for (int j = 0; j < 8; ++j)
                        acc[i][j] += a[i] * b[j];
            }
            __syncthreads();
        }
    }

    #pragma unroll
    for (int i = 0; i < 8; ++i) {
        int r = m0 + ty * 8 + i;
        if (r >= M) continue;
        #pragma unroll
        for (int j = 0; j < 8; ++j) {
            int c = n0 + tx * 8 + j;
            if (c >= Nout) continue;
            float v = acc[i][j] + bias[c];
            if (do_relu) v = fmaxf(v, 0.f);
            Y[(long)r * Nout + c] = v;
        }
    }
}

// ---------------- graph mean pooling ----------------
__global__ void k_pool(const float* __restrict__ h4, const int* __restrict__ gids) {
    int n = blockIdx.x * blockDim.x + threadIdx.x;
    if (n >= N_NODES) return;
    int g = gids[n];
    atomicAdd(&g_gcnt[g], 1);
    #pragma unroll
    for (int c = 0; c < 5; ++c)
        atomicAdd(&g_pool[g * 5 + c], h4[n * 5 + c]);
}

__global__ void k_final(float* __restrict__ out) {
    int i = blockIdx.x * blockDim.x + threadIdx.x;
    if (i < N_GRAPHS * 5) {
        int g = i / 5;
        int c = g_gcnt[g];
        out[i] = g_pool[i] / (float)(c > 0 ? c : 1);
    }
}

// ---------------- launch ----------------
extern "C" void kernel_launch(void* const* d_in, const int* in_sizes, int n_in,
                              void* d_out, int out_size)
{
    const float* in_feat = (const float*)d_in[0];
    const int*   src     = (const int*)d_in[1];
    const int*   dst     = (const int*)d_in[2];
    const int*   gids    = (const int*)d_in[3];
    const float* ws[4] = { (const float*)d_in[4],  (const float*)d_in[7],
                           (const float*)d_in[10], (const float*)d_in[13] };
    const float* wn[4] = { (const float*)d_in[5],  (const float*)d_in[8],
                           (const float*)d_in[11], (const float*)d_in[14] };
    const float* bs[4] = { (const float*)d_in[6],  (const float*)d_in[9],
                           (const float*)d_in[12], (const float*)d_in[15] };

    float *h1, *h2, *h3, *h4, *agg;
    cudaGetSymbolAddress((void**)&h1,  g_h1);
    cudaGetSymbolAddress((void**)&h2,  g_h2);
    cudaGetSymbolAddress((void**)&h3,  g_h3);
    cudaGetSymbolAddress((void**)&h4,  g_h4);
    cudaGetSymbolAddress((void**)&agg, g_agg);

    const int TB = 256;
    // CSR build (per call; deterministic work)
    k_zero<<<(N_NODES + TB - 1) / TB, TB>>>();
    k_count<<<(N_EDGES + TB - 1) / TB, TB>>>(dst);
    k_scan1<<<NB_SCAN, SCAN_B>>>();
    k_scan2<<<1, 32>>>(NB_SCAN);
    k_scan3<<<NB_SCAN, SCAN_B>>>();
    k_invdeg<<<(N_NODES + TB - 1) / TB, TB>>>();
    k_fill<<<(N_EDGES + TB - 1) / TB, TB>>>(src, dst);

    const int aggBlocks = (N_NODES + 7) / 8;   // 8 warps/block, warp per node
    const int gemmRows  = (N_NODES + 127) / 128;

    // layer 1: 128 -> 128, relu
    k_agg<<<aggBlocks, TB>>>(in_feat, 128);
    k_gemm<<<dim3(1, gemmRows), TB>>>(in_feat, agg, ws[0], wn[0], bs[0], h1,
                                      N_NODES, 128, 128, 1);
    // layer 2: 128 -> 118, relu
    k_agg<<<aggBlocks, TB>>>(h1, 128);
    k_gemm<<<dim3(1, gemmRows), TB>>>(h1, agg, ws[1], wn[1], bs[1], h2,
                                      N_NODES, 128, 118, 1);
    // layer 3: 118 -> 103, relu
    k_agg<<<aggBlocks, TB>>>(h2, 118);
    k_gemm<<<dim3(1, gemmRows), TB>>>(h2, agg, ws[2], wn[2], bs[2], h3,
                                      N_NODES, 118, 103, 1);
    // layer 4: 103 -> 5, no relu
    k_agg<<<aggBlocks, TB>>>(h3, 103);
    k_gemm<<<dim3(1, gemmRows), TB>>>(h3, agg, ws[3], wn[3], bs[3], h4,
                                      N_NODES, 103, 5, 0);

    // graph mean pooling
    k_pool<<<(N_NODES + TB - 1) / TB, TB>>>(h4, gids);
    k_final<<<1, 512>>>((float*)d_out);
}

// round 2
// speedup vs baseline: 1.0403x; 1.0403x over previous
#include <cuda_runtime.h>
#include <cuda_bf16.h>

#define N_NODES  100000
#define N_EDGES  1600000
#define N_GRAPHS 100
#define SCAN_B   1024
#define NB_SCAN  ((N_NODES + SCAN_B - 1) / SCAN_B)   // 98

// ---------------- scratch (static __device__ allocations only) ----------------
__device__ float g_hn[12800000];   // hn outputs (pitch <=128), also hn4 (pitch 8)
__device__ float g_hs[15200000];   // hs outputs (pitch <=152), also hs4 (pitch 8)
__device__ float g_ha[12800000];   // ping: h1 (pitch128), h3 (pitch104)
__device__ float g_hb[12800000];   // pong: h2 (pitch120), h4 (pitch 8)
__device__ float g_invdeg[N_NODES];
__device__ int   g_rowcnt[N_NODES];
__device__ int   g_rowptr[N_NODES];
__device__ int   g_cursor[N_NODES];
__device__ int   g_csr[N_EDGES];
__device__ int   g_bsum[128];
__device__ int   g_boff[128];
__device__ float g_pool[N_GRAPHS * 5];
__device__ int   g_gcnt[N_GRAPHS];

// ---------------- f32x2 packed FMA ----------------
__device__ __forceinline__ void fma2(unsigned long long& d,
                                     unsigned long long a,
                                     unsigned long long b) {
    asm("fma.rn.f32x2 %0, %1, %2, %0;" : "+l"(d) : "l"(a), "l"(b));
}
__device__ __forceinline__ unsigned long long dup_f(float v) {
    unsigned int b = __float_as_uint(v);
    return ((unsigned long long)b << 32) | (unsigned long long)b;
}
union U64F2 { unsigned long long u; float2 f; };

// ---------------- CSR build ----------------
__global__ void k_zero() {
    int i = blockIdx.x * blockDim.x + threadIdx.x;
    if (i < N_NODES) g_rowcnt[i] = 0;
    if (i < N_GRAPHS * 5) g_pool[i] = 0.f;
    if (i < N_GRAPHS) g_gcnt[i] = 0;
}

__global__ void k_count(const int* __restrict__ dst) {
    int e = blockIdx.x * blockDim.x + threadIdx.x;
    if (e < N_EDGES) atomicAdd(&g_rowcnt[dst[e]], 1);
}

__global__ void k_scan1() {
    __shared__ int s[SCAN_B];
    int tid = threadIdx.x;
    int gid = blockIdx.x * SCAN_B + tid;
    int v = (gid < N_NODES) ? g_rowcnt[gid] : 0;
    s[tid] = v;
    __syncthreads();
    for (int off = 1; off < SCAN_B; off <<= 1) {
        int t = (tid >= off) ? s[tid - off] : 0;
        __syncthreads();
        s[tid] += t;
        __syncthreads();
    }
    if (gid < N_NODES) g_rowptr[gid] = s[tid] - v;   // exclusive within block
    if (tid == SCAN_B - 1) g_bsum[blockIdx.x] = s[tid];
}

__global__ void k_scan2() {   // parallel scan over 98 block sums
    __shared__ int s[128];
    int t = threadIdx.x;
    int v = (t < NB_SCAN) ? g_bsum[t] : 0;
    s[t] = v;
    __syncthreads();
    for (int off = 1; off < 128; off <<= 1) {
        int x = (t >= off) ? s[t - off] : 0;
        __syncthreads();
        s[t] += x;
        __syncthreads();
    }
    if (t < NB_SCAN) g_boff[t] = s[t] - v;   // exclusive
}

__global__ void k_scan3() {   // finalize rowptr, init cursor, compute invdeg
    int gid = blockIdx.x * SCAN_B + threadIdx.x;
    if (gid < N_NODES) {
        int rp = g_rowptr[gid] + g_boff[blockIdx.x];
        g_rowptr[gid] = rp;
        g_cursor[gid] = rp;
        int c = g_rowcnt[gid];
        g_invdeg[gid] = 1.0f / (float)(c > 0 ? c : 1);
    }
}

__global__ void k_fill(const int* __restrict__ src, const int* __restrict__ dst) {
    int e = blockIdx.x * blockDim.x + threadIdx.x;
    if (e < N_EDGES) {
        int pos = atomicAdd(&g_cursor[dst[e]], 1);
        g_csr[pos] = src[e];
    }
}

// ---------------- dual-output GEMM with packed f32x2 FMA ----------------
// Logical: Y[M x 256] = A[M x K] @ Blog, where Blog cols [0,Pn) = Wn (zero-padded
// past dout), cols [Pn, 256) = Ws (zero-padded past dout). Y cols [0,Pn) -> Hn
// (pitch Pn), cols [Pn,256) -> Hs (pitch Ps). 128x256 tile, BK=8, 256 threads,
// per-thread 8 rows (4 f32x2 row-pairs) x 16 cols.
__global__ void __launch_bounds__(256)
k_gemm(const float* __restrict__ A, int lda, int M, int K,
       const float* __restrict__ Wn, const float* __restrict__ Ws,
       int dout, int Pn, int Ps,
       float* __restrict__ Hn, float* __restrict__ Hs)
{
    __shared__ float sA[8][132];
    __shared__ float sB[8][520];   // duplicated: sB[kk][2c],[2c+1] = B[c]

    const int tid = threadIdx.x;
    const int tx = tid & 15;       // row group: rows tx*8 .. tx*8+7
    const int ty = tid >> 4;       // col group: cols ty*16 .. ty*16+15
    const int m0 = blockIdx.x * 128;

    unsigned long long acc[4][16];
    #pragma unroll
    for (int i = 0; i < 4; ++i)
        #pragma unroll
        for (int j = 0; j < 16; ++j) acc[i][j] = 0ULL;

    const int ar = tid >> 3;       // 0..31 (row base, +32 per i)
    const int ak = tid & 7;        // kk for A loads
    float pa[4], pb[8];

    const int nt = (K + 7) >> 3;

    // prefetch tile 0
    {
        const int k0 = 0;
        #pragma unroll
        for (int i = 0; i < 4; ++i) {
            int gr = m0 + ar + 32 * i, gk = k0 + ak;
            pa[i] = (gr < M && gk < K) ? A[(size_t)gr * lda + gk] : 0.f;
        }
        #pragma unroll
        for (int i = 0; i < 8; ++i) {
            int gk = k0 + i;
            float v = 0.f;
            if (gk < K) {
                if (tid < Pn) { if (tid < dout) v = Wn[(size_t)gk * dout + tid]; }
                else { int cs = tid - Pn; if (cs < dout) v = Ws[(size_t)gk * dout + cs]; }
            }
            pb[i] = v;
        }
    }

    for (int t = 0; t < nt; ++t) {
        __syncthreads();
        #pragma unroll
        for (int i = 0; i < 4; ++i) sA[ak][ar + 32 * i] = pa[i];
        #pragma unroll
        for (int i = 0; i < 8; ++i)
            *(unsigned long long*)&sB[i][2 * tid] = dup_f(pb[i]);
        __syncthreads();

        if (t + 1 < nt) {
            const int k0 = (t + 1) << 3;
            #pragma unroll
            for (int i = 0; i < 4; ++i) {
                int gr = m0 + ar + 32 * i, gk = k0 + ak;
                pa[i] = (gr < M && gk < K) ? A[(size_t)gr * lda + gk] : 0.f;
            }
            #pragma unroll
            for (int i = 0; i < 8; ++i) {
                int gk = k0 + i;
                float v = 0.f;
                if (gk < K) {
                    if (tid < Pn) { if (tid < dout) v = Wn[(size_t)gk * dout + tid]; }
                    else { int cs = tid - Pn; if (cs < dout) v = Ws[(size_t)gk * dout + cs]; }
                }
                pb[i] = v;
            }
        }

        #pragma unroll
        for (int kk = 0; kk < 8; ++kk) {
            const ulonglong2* qa = (const ulonglong2*)&sA[kk][tx * 8];
            ulonglong2 a01 = qa[0], a23 = qa[1];
            unsigned long long a2[4] = { a01.x, a01.y, a23.x, a23.y };
            const ulonglong2* qb = (const ulonglong2*)&sB[kk][ty * 32];
            #pragma unroll
            for (int jq = 0; jq < 4; ++jq) {
                ulonglong2 b0 = qb[2 * jq], b1 = qb[2 * jq + 1];
                #pragma unroll
                for (int ip = 0; ip < 4; ++ip) {
                    fma2(acc[ip][4 * jq + 0], a2[ip], b0.x);
                    fma2(acc[ip][4 * jq + 1], a2[ip], b0.y);
                    fma2(acc[ip][4 * jq + 2], a2[ip], b1.x);
                    fma2(acc[ip][4 * jq + 3], a2[ip], b1.y);
                }
            }
        }
    }

    // epilogue: unpack pairs, float4 stores
    #pragma unroll
    for (int ip = 0; ip < 4; ++ip) {
        #pragma unroll
        for (int par = 0; par < 2; ++par) {
            int r = m0 + tx * 8 + 2 * ip + par;
            if (r >= M) continue;
            #pragma unroll
            for (int jq = 0; jq < 4; ++jq) {
                int c0 = ty * 16 + 4 * jq;
                float4 v;
                U64F2 u0, u1, u2, u3;
                u0.u = acc[ip][4 * jq + 0]; u1.u = acc[ip][4 * jq + 1];
                u2.u = acc[ip][4 * jq + 2]; u3.u = acc[ip][4 * jq + 3];
                v.x = par ? u0.f.y : u0.f.x;
                v.y = par ? u1.f.y : u1.f.x;
                v.z = par ? u2.f.y : u2.f.x;
                v.w = par ? u3.f.y : u3.f.x;
                if (c0 < Pn) *(float4*)&Hn[(size_t)r * Pn + c0] = v;
                else         *(float4*)&Hs[(size_t)r * Ps + (c0 - Pn)] = v;
            }
        }
    }
}

// ---------------- fused aggregation + epilogue ----------------
// h_out[n] = relu( hs[n] + invdeg[n] * sum_{s in N(n)} hn[s] + b )
template<int P4, int DOUT, int PN, int PS, int POUT, int RELU>
__global__ void k_agg(const float* __restrict__ Hn, const float* __restrict__ Hs,
                      const float* __restrict__ bias, float* __restrict__ Hout)
{
    int warp = (int)((blockIdx.x * blockDim.x + threadIdx.x) >> 5);
    int lane = threadIdx.x & 31;
    if (warp >= N_NODES) return;
    int beg = g_rowptr[warp];
    int cnt = g_rowcnt[warp];
    float4 s = make_float4(0.f, 0.f, 0.f, 0.f);
    int j = 0;
    for (; j + 2 <= cnt; j += 2) {
        int s0 = g_csr[beg + j];
        int s1 = g_csr[beg + j + 1];
        if (lane < P4) {
            float4 r0 = *(const float4*)&Hn[(size_t)s0 * PN + lane * 4];
            float4 r1 = *(const float4*)&Hn[(size_t)s1 * PN + lane * 4];
            s.x += r0.x + r1.x; s.y += r0.y + r1.y;
            s.z += r0.z + r1.z; s.w += r0.w + r1.w;
        }
    }
    if (j < cnt) {
        int s0 = g_csr[beg + j];
        if (lane < P4) {
            float4 r0 = *(const float4*)&Hn[(size_t)s0 * PN + lane * 4];
            s.x += r0.x; s.y += r0.y; s.z += r0.z; s.w += r0.w;
        }
    }
    if (lane < P4) {
        float inv = g_invdeg[warp];
        float sv[4] = { s.x, s.y, s.z, s.w };
        #pragma unroll
        for (int t = 0; t < 4; ++t) {
            int c = lane * 4 + t;
            float val = 0.f;
            if (c < DOUT) {
                val = Hs[(size_t)warp * PS + c] + sv[t] * inv + bias[c];
                if (RELU) val = fmaxf(val, 0.f);
            }
            Hout[(size_t)warp * POUT + c] = val;
        }
    }
}

// ---------------- layer 4: tiny GEMM (N=10) ----------------
__global__ void k_gemm4(const float* __restrict__ h3,
                        const float* __restrict__ ws4, const float* __restrict__ wn4,
                        float* __restrict__ hs4, float* __restrict__ hn4)
{
    __shared__ float sW[1030];   // [k][c10]
    int tid = threadIdx.x;
    for (int idx = tid; idx < 1030; idx += 256) {
        int k = idx / 10, c = idx % 10;
        sW[idx] = (c < 5) ? ws4[k * 5 + c] : wn4[k * 5 + (c - 5)];
    }
    __syncthreads();
    int node = blockIdx.x * 16 + (tid >> 4);
    int c = tid & 15;
    if (node >= N_NODES || c >= 10) return;
    const float* row = h3 + (size_t)node * 104;
    float acc = 0.f;
    #pragma unroll 4
    for (int k = 0; k < 103; ++k) acc += row[k] * sW[k * 10 + c];
    if (c < 5) hs4[node * 8 + c] = acc;
    else       hn4[node * 8 + (c - 5)] = acc;
}

// layer 4 aggregation: h4[n] = hs4[n] + inv * sum hn4[src] + b4  (no relu)
__global__ void k_agg4(const float* __restrict__ hn4, const float* __restrict__ hs4,
                       const float* __restrict__ b4, float* __restrict__ h4)
{
    int n = blockIdx.x * blockDim.x + threadIdx.x;
    if (n >= N_NODES) return;
    int beg = g_rowptr[n], cnt = g_rowcnt[n];
    float a0 = 0.f, a1 = 0.f, a2 = 0.f, a3 = 0.f, a4 = 0.f;
    for (int j = 0; j < cnt; ++j) {
        const float* r = hn4 + (size_t)g_csr[beg + j] * 8;
        a0 += __ldg(r + 0); a1 += __ldg(r + 1); a2 += __ldg(r + 2);
        a3 += __ldg(r + 3); a4 += __ldg(r + 4);
    }
    float inv = g_invdeg[n];
    h4[n * 8 + 0] = hs4[n * 8 + 0] + inv * a0 + b4[0];
    h4[n * 8 + 1] = hs4[n * 8 + 1] + inv * a1 + b4[1];
    h4[n * 8 + 2] = hs4[n * 8 + 2] + inv * a2 + b4[2];
    h4[n * 8 + 3] = hs4[n * 8 + 3] + inv * a3 + b4[3];
    h4[n * 8 + 4] = hs4[n * 8 + 4] + inv * a4 + b4[4];
}

// ---------------- graph mean pooling ----------------
__global__ void k_pool(const float* __restrict__ h4, const int* __restrict__ gids) {
    int n = blockIdx.x * blockDim.x + threadIdx.x;
    if (n >= N_NODES) return;
    int g = gids[n];
    atomicAdd(&g_gcnt[g], 1);
    #pragma unroll
    for (int c = 0; c < 5; ++c)
        atomicAdd(&g_pool[g * 5 + c], h4[n * 8 + c]);
}

__global__ void k_final(float* __restrict__ out) {
    int i = blockIdx.x * blockDim.x + threadIdx.x;
    if (i < N_GRAPHS * 5) {
        int g = i / 5;
        int c = g_gcnt[g];
        out[i] = g_pool[i] / (float)(c > 0 ? c : 1);
    }
}

// ---------------- launch ----------------
extern "C" void kernel_launch(void* const* d_in, const int* in_sizes, int n_in,
                              void* d_out, int out_size)
{
    const float* in_feat = (const float*)d_in[0];
    const int*   src     = (const int*)d_in[1];
    const int*   dst     = (const int*)d_in[2];
    const int*   gids    = (const int*)d_in[3];
    const float* ws[4] = { (const float*)d_in[4],  (const float*)d_in[7],
                           (const float*)d_in[10], (const float*)d_in[13] };
    const float* wn[4] = { (const float*)d_in[5],  (const float*)d_in[8],
                           (const float*)d_in[11], (const float*)d_in[14] };
    const float* bs[4] = { (const float*)d_in[6],  (const float*)d_in[9],
                           (const float*)d_in[12], (const float*)d_in[15] };

    float *hn, *hs, *ha, *hb;
    cudaGetSymbolAddress((void**)&hn, g_hn);
    cudaGetSymbolAddress((void**)&hs, g_hs);
    cudaGetSymbolAddress((void**)&ha, g_ha);
    cudaGetSymbolAddress((void**)&hb, g_hb);

    const int TB = 256;
    // CSR build
    k_zero<<<(N_NODES + TB - 1) / TB, TB>>>();
    k_count<<<(N_EDGES + TB - 1) / TB, TB>>>(dst);
    k_scan1<<<NB_SCAN, SCAN_B>>>();
    k_scan2<<<1, 128>>>();
    k_scan3<<<NB_SCAN, SCAN_B>>>();
    k_fill<<<(N_EDGES + TB - 1) / TB, TB>>>(src, dst);

    const int gemmRows  = (N_NODES + 127) / 128;   // 782
    const int aggBlocks = (N_NODES + 7) / 8;       // warp per node

    // layer 1: in_feat(128) -> h1(128), relu.  Pn=128, Ps=128
    k_gemm<<<gemmRows, TB>>>(in_feat, 128, N_NODES, 128, wn[0], ws[0],
                             128, 128, 128, hn, hs);
    k_agg<32, 128, 128, 128, 128, 1><<<aggBlocks, TB>>>(hn, hs, bs[0], ha);

    // layer 2: h1(128) -> h2(118, pitch120), relu.  Pn=120, Ps=136
    k_gemm<<<gemmRows, TB>>>(ha, 128, N_NODES, 128, wn[1], ws[1],
                             118, 120, 136, hn, hs);
    k_agg<30, 118, 120, 136, 120, 1><<<aggBlocks, TB>>>(hn, hs, bs[1], hb);

    // layer 3: h2(118, lda120) -> h3(103, pitch104), relu.  Pn=104, Ps=152
    k_gemm<<<gemmRows, TB>>>(hb, 120, N_NODES, 118, wn[2], ws[2],
                             103, 104, 152, hn, hs);
    k_agg<26, 103, 104, 152, 104, 1><<<aggBlocks, TB>>>(hn, hs, bs[2], ha);

    // layer 4: h3(103, lda104) -> h4(5, pitch8), no relu
    k_gemm4<<<(N_NODES + 15) / 16, TB>>>(ha, ws[3], wn[3], hs, hn);
    k_agg4<<<(N_NODES + TB - 1) / TB, TB>>>(hn, hs, bs[3], hb);

    // graph mean pooling
    k_pool<<<(N_NODES + TB - 1) / TB, TB>>>(hb, gids);
    k_final<<<1, 512>>>((float*)d_out);
}

// round 4
// speedup vs baseline: 1.7878x; 1.7185x over previous
#include <cuda_runtime.h>
#include <cuda_bf16.h>
#include <cstdint>

#define N_NODES  100000
#define N_PAD    100096          // 782 * 128
#define N_EDGES  1600000
#define N_GRAPHS 100
#define SCAN_B   1024
#define NB_SCAN  98

// ---------------- scratch (static __device__ allocations only) ----------------
__device__ __nv_bfloat16 g_ah[N_PAD * 128];   // A hi plane (pitch 128)
__device__ __nv_bfloat16 g_al[N_PAD * 128];   // A lo plane
__device__ __nv_bfloat16 g_bh[256 * 128];     // B hi plane [n][k]
__device__ __nv_bfloat16 g_bl[256 * 128];     // B lo plane
__device__ float g_y[N_PAD * 256];            // GEMM out: cols [0,128)=Hn, [128,256)=Hs
__device__ float g_h3[N_NODES * 104];         // layer-3 activation (fp32, pitch 104)
__device__ float g_h4[N_NODES * 8];           // final node features (pitch 8)
__device__ float g_invdeg[N_NODES];
__device__ int   g_rowcnt[N_NODES];
__device__ int   g_rowptr[N_NODES];
__device__ int   g_cursor[N_NODES];
__device__ int   g_csr[N_EDGES];
__device__ int   g_bsum[128];
__device__ int   g_boff[128];
__device__ float g_pool[N_GRAPHS * 5];
__device__ int   g_gcnt[N_GRAPHS];

// ---------------- PTX helpers ----------------
__device__ __forceinline__ uint32_t smem_u32(const void* p) {
    uint32_t a;
    asm("{ .reg .u64 t; cvta.to.shared.u64 t, %1; cvt.u32.u64 %0, t; }" : "=r"(a) : "l"(p));
    return a;
}

__device__ __forceinline__ void ldsm4(uint32_t* r, uint32_t addr) {
    asm volatile("ldmatrix.sync.aligned.m8n8.x4.shared.b16 {%0,%1,%2,%3}, [%4];"
                 : "=r"(r[0]), "=r"(r[1]), "=r"(r[2]), "=r"(r[3]) : "r"(addr));
}

__device__ __forceinline__ void mma16816(float* c, const uint32_t* a,
                                         uint32_t b0, uint32_t b1) {
    asm volatile(
        "mma.sync.aligned.m16n8k16.row.col.f32.bf16.bf16.f32 "
        "{%0,%1,%2,%3}, {%4,%5,%6,%7}, {%8,%9}, {%0,%1,%2,%3};"
        : "+f"(c[0]), "+f"(c[1]), "+f"(c[2]), "+f"(c[3])
        : "r"(a[0]), "r"(a[1]), "r"(a[2]), "r"(a[3]), "r"(b0), "r"(b1));
}

// ---------------- CSR build ----------------
__global__ void k_zero() {
    int i = blockIdx.x * blockDim.x + threadIdx.x;
    if (i < N_NODES) g_rowcnt[i] = 0;
    if (i < N_GRAPHS * 5) g_pool[i] = 0.f;
    if (i < N_GRAPHS) g_gcnt[i] = 0;
}

__global__ void k_count(const int* __restrict__ dst) {
    int e = blockIdx.x * blockDim.x + threadIdx.x;
    if (e < N_EDGES) atomicAdd(&g_rowcnt[dst[e]], 1);
}

__global__ void k_scan1() {
    __shared__ int s[SCAN_B];
    int tid = threadIdx.x;
    int gid = blockIdx.x * SCAN_B + tid;
    int v = (gid < N_NODES) ? g_rowcnt[gid] : 0;
    s[tid] = v;
    __syncthreads();
    for (int off = 1; off < SCAN_B; off <<= 1) {
        int t = (tid >= off) ? s[tid - off] : 0;
        __syncthreads();
        s[tid] += t;
        __syncthreads();
    }
    if (gid < N_NODES) g_rowptr[gid] = s[tid] - v;
    if (tid == SCAN_B - 1) g_bsum[blockIdx.x] = s[tid];
}

__global__ void k_scan2() {
    __shared__ int s[128];
    int t = threadIdx.x;
    int v = (t < NB_SCAN) ? g_bsum[t] : 0;
    s[t] = v;
    __syncthreads();
    for (int off = 1; off < 128; off <<= 1) {
        int x = (t >= off) ? s[t - off] : 0;
        __syncthreads();
        s[t] += x;
        __syncthreads();
    }
    if (t < NB_SCAN) g_boff[t] = s[t] - v;
}

__global__ void k_scan3() {
    int gid = blockIdx.x * SCAN_B + threadIdx.x;
    if (gid < N_NODES) {
        int rp = g_rowptr[gid] + g_boff[blockIdx.x];
        g_rowptr[gid] = rp;
        g_cursor[gid] = rp;
        int c = g_rowcnt[gid];
        g_invdeg[gid] = 1.0f / (float)(c > 0 ? c : 1);
    }
}

__global__ void k_fill(const int* __restrict__ src, const int* __restrict__ dst) {
    int e = blockIdx.x * blockDim.x + threadIdx.x;
    if (e < N_EDGES) {
        int pos = atomicAdd(&g_cursor[dst[e]], 1);
        g_csr[pos] = src[e];
    }
}

// ---------------- input / weight conversion to bf16 hi/lo ----------------
__device__ __forceinline__ void split_bf(float v, __nv_bfloat16& h, __nv_bfloat16& l) {
    h = __float2bfloat16(v);
    l = __float2bfloat16(v - __bfloat162float(h));
}

__global__ void k_conv_in(const float* __restrict__ x) {
    int idx = blockIdx.x * blockDim.x + threadIdx.x;   // N_PAD*128
    int n = idx >> 7;
    float v = (n < N_NODES) ? x[idx] : 0.f;
    __nv_bfloat16 h, l;
    split_bf(v, h, l);
    g_ah[idx] = h;
    g_al[idx] = l;
}

// B[n][k] = Wn[k][n] (n<128) | Ws[k][n-128], zero-padded
__global__ void k_wconv(const float* __restrict__ Wn, const float* __restrict__ Ws,
                        int K, int dout) {
    int idx = blockIdx.x * blockDim.x + threadIdx.x;   // 256*128
    int n = idx >> 7, k = idx & 127;
    float v = 0.f;
    if (k < K) {
        if (n < 128) { if (n < dout) v = Wn[k * dout + n]; }
        else { int s = n - 128; if (s < dout) v = Ws[k * dout + s]; }
    }
    __nv_bfloat16 h, l;
    split_bf(v, h, l);
    g_bh[idx] = h;
    g_bl[idx] = l;
}

// ---------------- HMMA GEMM: Y[M x 256] = (Ahi+Alo) @ (Bhi+Blo)^T ----------------
// Per CTA: 128x256 tile, full K=128 resident in smem (4 planes).
// 8 warps in 2(m) x 4(n) grid, 64x64 warp tile, mma.sync m16n8k16 bf16.
#define APITCH 272                 // bytes per row (68 words; %32 == 4 -> conflict-free)
#define SM_AH  0
#define SM_AL  34816               // 128*272
#define SM_BH  69632
#define SM_BL  139264              // 69632 + 256*272
#define GEMM_SMEM 208896

__global__ void __launch_bounds__(256, 1)
k_gemm_mma(const __nv_bfloat16* __restrict__ ah, const __nv_bfloat16* __restrict__ al,
           const __nv_bfloat16* __restrict__ bh, const __nv_bfloat16* __restrict__ bl,
           float* __restrict__ Y)
{
    extern __shared__ char smem[];
    const int tid = threadIdx.x;
    const int m0 = blockIdx.x * 128;

    // fill smem: A 128 rows x 256B, B 256 rows x 256B, 16B per thread-chunk
    {
        const int c = tid & 15;          // chunk within row
        const int r0 = tid >> 4;         // 16 rows per pass
        #pragma unroll
        for (int i = 0; i < 8; ++i) {
            int row = r0 + i * 16;
            size_t g = (size_t)(m0 + row) * 128 + c * 8;
            *(uint4*)(smem + SM_AH + row * APITCH + c * 16) = *(const uint4*)(ah + g);
            *(uint4*)(smem + SM_AL + row * APITCH + c * 16) = *(const uint4*)(al + g);
        }
        #pragma unroll
        for (int i = 0; i < 16; ++i) {
            int row = r0 + i * 16;
            size_t g = (size_t)row * 128 + c * 8;
            *(uint4*)(smem + SM_BH + row * APITCH + c * 16) = *(const uint4*)(bh + g);
            *(uint4*)(smem + SM_BL + row * APITCH + c * 16) = *(const uint4*)(bl + g);
        }
    }
    __syncthreads();

    const int wid = tid >> 5, lane = tid & 31;
    const int wm = (wid & 1) * 64;       // warp row offset
    const int wn = (wid >> 1) * 64;      // warp col offset

    float acc[4][8][4];
    #pragma unroll
    for (int mf = 0; mf < 4; ++mf)
        #pragma unroll
        for (int nf = 0; nf < 8; ++nf)
            #pragma unroll
            for (int q = 0; q < 4; ++q) acc[mf][nf][q] = 0.f;

    const uint32_t sb = smem_u32(smem);
    // ldmatrix lane addressing
    const uint32_t aAddr = sb + (uint32_t)(wm + (lane & 15)) * APITCH + (lane >> 4) * 16;
    const uint32_t bAddr = sb + (uint32_t)(wn + (lane & 7) + ((lane >> 4) << 3)) * APITCH
                              + ((lane >> 3) & 1) * 16;

    #pragma unroll
    for (int ks = 0; ks < 8; ++ks) {
        const uint32_t kb = ks * 32;
        uint32_t Ah[4][4], Al[4][4];
        #pragma unroll
        for (int mf = 0; mf < 4; ++mf) {
            ldsm4(Ah[mf], aAddr + SM_AH + mf * (16 * APITCH) + kb);
            ldsm4(Al[mf], aAddr + SM_AL + mf * (16 * APITCH) + kb);
        }
        #pragma unroll
        for (int nq = 0; nq < 4; ++nq) {     // each nq covers 2 n8-frags
            uint32_t Bh4[4], Bl4[4];
            ldsm4(Bh4, bAddr + SM_BH + nq * (16 * APITCH) + kb);
            ldsm4(Bl4, bAddr + SM_BL + nq * (16 * APITCH) + kb);
            #pragma unroll
            for (int mf = 0; mf < 4; ++mf) {
                float* c0 = acc[mf][2 * nq];
                float* c1 = acc[mf][2 * nq + 1];
                mma16816(c0, Ah[mf], Bh4[0], Bh4[1]);   // hi*hi
                mma16816(c0, Ah[mf], Bl4[0], Bl4[1]);   // hi*lo
                mma16816(c0, Al[mf], Bh4[0], Bh4[1]);   // lo*hi
                mma16816(c1, Ah[mf], Bh4[2], Bh4[3]);
                mma16816(c1, Ah[mf], Bl4[2], Bl4[3]);
                mma16816(c1, Al[mf], Bh4[2], Bh4[3]);
            }
        }
    }

    // epilogue: fragment -> Y (rows < N_PAD always; Y sized N_PAD*256)
    const int gid = lane >> 2, tig = lane & 3;
    #pragma unroll
    for (int mf = 0; mf < 4; ++mf) {
        int r = m0 + wm + mf * 16 + gid;
        #pragma unroll
        for (int nf = 0; nf < 8; ++nf) {
            int col = wn + nf * 8 + tig * 2;
            *(float2*)&Y[(size_t)r * 256 + col] =
                make_float2(acc[mf][nf][0], acc[mf][nf][1]);
            *(float2*)&Y[(size_t)(r + 8) * 256 + col] =
                make_float2(acc[mf][nf][2], acc[mf][nf][3]);
        }
    }
}

// ---------------- fused aggregation + epilogue ----------------
// h = relu?( Y[:,128+c] + invdeg * sum_{s in N(n)} Y[s, c] + b[c] )
// OUTBF=1: write bf16 hi/lo planes (pitch 128); else fp32 pitch 104.
template<int DOUT, int RELU, int OUTBF>
__global__ void k_agg(const float* __restrict__ Y, const float* __restrict__ bias,
                      __nv_bfloat16* __restrict__ oh, __nv_bfloat16* __restrict__ ol,
                      float* __restrict__ of)
{
    int warp = (int)((blockIdx.x * blockDim.x + threadIdx.x) >> 5);
    int lane = threadIdx.x & 31;
    if (warp >= N_NODES) return;
    int beg = g_rowptr[warp];
    int cnt = g_rowcnt[warp];
    const int NL = (DOUT + 3) >> 2;
    const bool act = lane < NL;
    const int c = lane * 4;

    float4 s = make_float4(0.f, 0.f, 0.f, 0.f);
    int j = 0;
    for (; j + 2 <= cnt; j += 2) {
        int s0 = g_csr[beg + j];
        int s1 = g_csr[beg + j + 1];
        if (act) {
            float4 r0 = *(const float4*)(Y + (size_t)s0 * 256 + c);
            float4 r1 = *(const float4*)(Y + (size_t)s1 * 256 + c);
            s.x += r0.x + r1.x; s.y += r0.y + r1.y;
            s.z += r0.z + r1.z; s.w += r0.w + r1.w;
        }
    }
    if (j < cnt) {
        int s0 = g_csr[beg + j];
        if (act) {
            float4 r0 = *(const float4*)(Y + (size_t)s0 * 256 + c);
            s.x += r0.x; s.y += r0.y; s.z += r0.z; s.w += r0.w;
        }
    }

    float v[4] = { 0.f, 0.f, 0.f, 0.f };
    if (act) {
        float inv = g_invdeg[warp];
        const float* self = Y + (size_t)warp * 256 + 128 + c;
        float sv[4] = { s.x, s.y, s.z, s.w };
        #pragma unroll
        for (int t = 0; t < 4; ++t) {
            int cc = c + t;
            if (cc < DOUT) {
                float x = self[t] + sv[t] * inv + bias[cc];
                v[t] = RELU ? fmaxf(x, 0.f) : x;
            }
        }
    }

    if (OUTBF) {
        if (act) {
            union { __nv_bfloat162 b2[2]; uint2 u; } uh, ul;
            #pragma unroll
            for (int t = 0; t < 2; ++t) {
                __nv_bfloat16 h0, l0, h1, l1;
                split_bf(v[2*t], h0, l0);
                split_bf(v[2*t+1], h1, l1);
                uh.b2[t] = __nv_bfloat162(h0, h1);
                ul.b2[t] = __nv_bfloat162(l0, l1);
            }
            *(uint2*)(oh + (size_t)warp * 128 + c) = uh.u;
            *(uint2*)(ol + (size_t)warp * 128 + c) = ul.u;
        }
    } else {
        if (act && c < 104)
            *(float4*)(of + (size_t)warp * 104 + c) = make_float4(v[0], v[1], v[2], v[3]);
    }
}

// ---------------- layer 4: tiny GEMM (N=10) + agg ----------------
__global__ void k_gemm4(const float* __restrict__ h3,
                        const float* __restrict__ ws4, const float* __restrict__ wn4,
                        float* __restrict__ hs4, float* __restrict__ hn4)
{
    __shared__ float sW[1030];
    int tid = threadIdx.x;
    for (int idx = tid; idx < 1030; idx += 256) {
        int k = idx / 10, cc = idx % 10;
        sW[idx] = (cc < 5) ? ws4[k * 5 + cc] : wn4[k * 5 + (cc - 5)];
    }
    __syncthreads();
    int node = blockIdx.x * 16 + (tid >> 4);
    int cc = tid & 15;
    if (node >= N_NODES || cc >= 10) return;
    const float* row = h3 + (size_t)node * 104;
    float acc = 0.f;
    #pragma unroll 4
    for (int k = 0; k < 103; ++k) acc += row[k] * sW[k * 10 + cc];
    if (cc < 5) hs4[node * 8 + cc] = acc;
    else        hn4[node * 8 + (cc - 5)] = acc;
}

__global__ void k_agg4(const float* __restrict__ hn4, const float* __restrict__ hs4,
                       const float* __restrict__ b4, float* __restrict__ h4)
{
    int n = blockIdx.x * blockDim.x + threadIdx.x;
    if (n >= N_NODES) return;
    int beg = g_rowptr[n], cnt = g_rowcnt[n];
    float a0 = 0.f, a1 = 0.f, a2 = 0.f, a3 = 0.f, a4 = 0.f;
    for (int j = 0; j < cnt; ++j) {
        const float* r = hn4 + (size_t)g_csr[beg + j] * 8;
        a0 += __ldg(r + 0); a1 += __ldg(r + 1); a2 += __ldg(r + 2);
        a3 += __ldg(r + 3); a4 += __ldg(r + 4);
    }
    float inv = g_invdeg[n];
    h4[n * 8 + 0] = hs4[n * 8 + 0] + inv * a0 + b4[0];
    h4[n * 8 + 1] = hs4[n * 8 + 1] + inv * a1 + b4[1];
    h4[n * 8 + 2] = hs4[n * 8 + 2] + inv * a2 + b4[2];
    h4[n * 8 + 3] = hs4[n * 8 + 3] + inv * a3 + b4[3];
    h4[n * 8 + 4] = hs4[n * 8 + 4] + inv * a4 + b4[4];
}

// ---------------- graph mean pooling ----------------
__global__ void k_pool(const float* __restrict__ h4, const int* __restrict__ gids) {
    int n = blockIdx.x * blockDim.x + threadIdx.x;
    if (n >= N_NODES) return;
    int g = gids[n];
    atomicAdd(&g_gcnt[g], 1);
    #pragma unroll
    for (int cc = 0; cc < 5; ++cc)
        atomicAdd(&g_pool[g * 5 + cc], h4[n * 8 + cc]);
}

__global__ void k_final(float* __restrict__ out) {
    int i = blockIdx.x * blockDim.x + threadIdx.x;
    if (i < N_GRAPHS * 5) {
        int g = i / 5;
        int c = g_gcnt[g];
        out[i] = g_pool[i] / (float)(c > 0 ? c : 1);
    }
}

// ---------------- launch ----------------
extern "C" void kernel_launch(void* const* d_in, const int* in_sizes, int n_in,
                              void* d_out, int out_size)
{
    const float* in_feat = (const float*)d_in[0];
    const int*   src     = (const int*)d_in[1];
    const int*   dst     = (const int*)d_in[2];
    const int*   gids    = (const int*)d_in[3];
    const float* ws[4] = { (const float*)d_in[4],  (const float*)d_in[7],
                           (const float*)d_in[10], (const float*)d_in[13] };
    const float* wn[4] = { (const float*)d_in[5],  (const float*)d_in[8],
                           (const float*)d_in[11], (const float*)d_in[14] };
    const float* bs[4] = { (const float*)d_in[6],  (const float*)d_in[9],
                           (const float*)d_in[12], (const float*)d_in[15] };

    __nv_bfloat16 *ah, *al, *bh, *bl;
    float *y, *h3, *h4;
    cudaGetSymbolAddress((void**)&ah, g_ah);
    cudaGetSymbolAddress((void**)&al, g_al);
    cudaGetSymbolAddress((void**)&bh, g_bh);
    cudaGetSymbolAddress((void**)&bl, g_bl);
    cudaGetSymbolAddress((void**)&y,  g_y);
    cudaGetSymbolAddress((void**)&h3, g_h3);
    cudaGetSymbolAddress((void**)&h4, g_h4);
    float* hs4 = y;                 // g_y free after agg3
    float* hn4 = y + 800000;

    cudaFuncSetAttribute(k_gemm_mma, cudaFuncAttributeMaxDynamicSharedMemorySize, GEMM_SMEM);

    const int TB = 256;
    const int gemmGrid = N_PAD / 128;               // 782
    const int aggBlocks = (N_NODES + 7) / 8;        // warp per node

    k_zero<<<(N_NODES + TB - 1) / TB, TB>>>();                               // 0
    k_wconv<<<128, TB>>>(wn[0], ws[0], 128, 128);                            // 1
    k_conv_in<<<(N_PAD * 128) / TB, TB>>>(in_feat);                          // 2
    k_gemm_mma<<<gemmGrid, TB, GEMM_SMEM>>>(ah, al, bh, bl, y);              // 3 (profiled)
    k_count<<<(N_EDGES + TB - 1) / TB, TB>>>(dst);                           // 4
    k_scan1<<<NB_SCAN, SCAN_B>>>();                                          // 5
    k_scan2<<<1, 128>>>();                                                   // 6
    k_scan3<<<NB_SCAN, SCAN_B>>>();                                          // 7
    k_fill<<<(N_EDGES + TB - 1) / TB, TB>>>(src, dst);                       // 8

    // layer 1 epilogue -> bf16 planes for layer 2
    k_agg<128, 1, 1><<<aggBlocks, TB>>>(y, bs[0], ah, al, nullptr);          // 9
    // layer 2
    k_wconv<<<128, TB>>>(wn[1], ws[1], 128, 118);                            // 10
    k_gemm_mma<<<gemmGrid, TB, GEMM_SMEM>>>(ah, al, bh, bl, y);              // 11
    k_agg<118, 1, 1><<<aggBlocks, TB>>>(y, bs[1], ah, al, nullptr);          // 12
    // layer 3
    k_wconv<<<128, TB>>>(wn[2], ws[2], 118, 103);                            // 13
    k_gemm_mma<<<gemmGrid, TB, GEMM_SMEM>>>(ah, al, bh, bl, y);              // 14
    k_agg<103, 1, 0><<<aggBlocks, TB>>>(y, bs[2], nullptr, nullptr, h3);     // 15
    // layer 4 (SIMT, tiny)
    k_gemm4<<<(N_NODES + 15) / 16, TB>>>(h3, ws[3], wn[3], hs4, hn4);        // 16
    k_agg4<<<(N_NODES + TB - 1) / TB, TB>>>(hn4, hs4, bs[3], h4);            // 17
    // pooling
    k_pool<<<(N_NODES + TB - 1) / TB, TB>>>(h4, gids);                       // 18
    k_final<<<1, 512>>>((float*)d_out);                                      // 19
}

// round 5
// speedup vs baseline: 1.9864x; 1.1111x over previous
#include <cuda_runtime.h>
#include <cuda_bf16.h>
#include <cuda_fp16.h>
#include <cstdint>

#define N_NODES  100000
#define N_PAD    100096          // 782 * 128
#define N_EDGES  1600000
#define N_GRAPHS 100
#define SCAN_B   1024
#define NB_SCAN  98

// ---------------- scratch (static __device__ allocations only) ----------------
__device__ __nv_bfloat16 g_ah[N_PAD * 128];   // A hi plane (pitch 128)
__device__ __nv_bfloat16 g_al[N_PAD * 128];   // A lo plane
__device__ __nv_bfloat16 g_bh[256 * 128];     // B hi plane [n][k]
__device__ __nv_bfloat16 g_bl[256 * 128];     // B lo plane
__device__ __half g_yn[N_PAD * 128];          // neighbor-transform out (fp16, pitch 128)
__device__ float  g_ys[N_PAD * 128];          // self-transform out (fp32, pitch 128)
__device__ float  g_h3[N_NODES * 104];        // layer-3 activation (fp32, pitch 104)
__device__ float  g_h4[N_NODES * 8];          // final node features (pitch 8)
__device__ float g_invdeg[N_NODES];
__device__ int   g_rowcnt[N_NODES];
__device__ int   g_rowptr[N_NODES];
__device__ int   g_cursor[N_NODES];
__device__ int   g_csr[N_EDGES];
__device__ int   g_bsum[128];
__device__ int   g_boff[128];
__device__ float g_pool[N_GRAPHS * 5];
__device__ int   g_gcnt[N_GRAPHS];

// ---------------- PTX helpers ----------------
__device__ __forceinline__ uint32_t smem_u32(const void* p) {
    uint32_t a;
    asm("{ .reg .u64 t; cvta.to.shared.u64 t, %1; cvt.u32.u64 %0, t; }" : "=r"(a) : "l"(p));
    return a;
}
__device__ __forceinline__ void ldsm4(uint32_t* r, uint32_t addr) {
    asm volatile("ldmatrix.sync.aligned.m8n8.x4.shared.b16 {%0,%1,%2,%3}, [%4];"
                 : "=r"(r[0]), "=r"(r[1]), "=r"(r[2]), "=r"(r[3]) : "r"(addr));
}
__device__ __forceinline__ void mma16816(float* c, const uint32_t* a,
                                         uint32_t b0, uint32_t b1) {
    asm volatile(
        "mma.sync.aligned.m16n8k16.row.col.f32.bf16.bf16.f32 "
        "{%0,%1,%2,%3}, {%4,%5,%6,%7}, {%8,%9}, {%0,%1,%2,%3};"
        : "+f"(c[0]), "+f"(c[1]), "+f"(c[2]), "+f"(c[3])
        : "r"(a[0]), "r"(a[1]), "r"(a[2]), "r"(a[3]), "r"(b0), "r"(b1));
}
__device__ __forceinline__ void cpa16(uint32_t d, const void* g) {
    asm volatile("cp.async.cg.shared.global [%0], [%1], 16;" :: "r"(d), "l"(g));
}
__device__ __forceinline__ void cp_commit() {
    asm volatile("cp.async.commit_group;" ::: "memory");
}
template<int N> __device__ __forceinline__ void cp_wait() {
    asm volatile("cp.async.wait_group %0;" :: "n"(N) : "memory");
}

// ---------------- CSR build ----------------
__global__ void k_zero() {
    int i = blockIdx.x * blockDim.x + threadIdx.x;
    if (i < N_NODES) g_rowcnt[i] = 0;
    if (i < N_GRAPHS * 5) g_pool[i] = 0.f;
    if (i < N_GRAPHS) g_gcnt[i] = 0;
}

__global__ void k_count(const int* __restrict__ dst) {
    int e = blockIdx.x * blockDim.x + threadIdx.x;
    if (e < N_EDGES) atomicAdd(&g_rowcnt[dst[e]], 1);
}

__global__ void k_scan1() {
    __shared__ int s[SCAN_B];
    int tid = threadIdx.x;
    int gid = blockIdx.x * SCAN_B + tid;
    int v = (gid < N_NODES) ? g_rowcnt[gid] : 0;
    s[tid] = v;
    __syncthreads();
    for (int off = 1; off < SCAN_B; off <<= 1) {
        int t = (tid >= off) ? s[tid - off] : 0;
        __syncthreads();
        s[tid] += t;
        __syncthreads();
    }
    if (gid < N_NODES) g_rowptr[gid] = s[tid] - v;
    if (tid == SCAN_B - 1) g_bsum[blockIdx.x] = s[tid];
}

__global__ void k_scan2() {
    __shared__ int s[128];
    int t = threadIdx.x;
    int v = (t < NB_SCAN) ? g_bsum[t] : 0;
    s[t] = v;
    __syncthreads();
    for (int off = 1; off < 128; off <<= 1) {
        int x = (t >= off) ? s[t - off] : 0;
        __syncthreads();
        s[t] += x;
        __syncthreads();
    }
    if (t < NB_SCAN) g_boff[t] = s[t] - v;
}

__global__ void k_scan3() {
    int gid = blockIdx.x * SCAN_B + threadIdx.x;
    if (gid < N_NODES) {
        int rp = g_rowptr[gid] + g_boff[blockIdx.x];
        g_rowptr[gid] = rp;
        g_cursor[gid] = rp;
        int c = g_rowcnt[gid];
        g_invdeg[gid] = 1.0f / (float)(c > 0 ? c : 1);
    }
}

__global__ void k_fill(const int* __restrict__ src, const int* __restrict__ dst) {
    int e = blockIdx.x * blockDim.x + threadIdx.x;
    if (e < N_EDGES) {
        int pos = atomicAdd(&g_cursor[dst[e]], 1);
        g_csr[pos] = src[e];
    }
}

// ---------------- input / weight conversion to bf16 hi/lo ----------------
__device__ __forceinline__ void split_bf(float v, __nv_bfloat16& h, __nv_bfloat16& l) {
    h = __float2bfloat16(v);
    l = __float2bfloat16(v - __bfloat162float(h));
}

__global__ void k_conv_in(const float* __restrict__ x) {
    int idx = blockIdx.x * blockDim.x + threadIdx.x;   // N_PAD*128
    int n = idx >> 7;
    float v = (n < N_NODES) ? x[idx] : 0.f;
    __nv_bfloat16 h, l;
    split_bf(v, h, l);
    g_ah[idx] = h;
    g_al[idx] = l;
}

// B[n][k] = Wn[k][n] (n<128) | Ws[k][n-128], zero-padded
__global__ void k_wconv(const float* __restrict__ Wn, const float* __restrict__ Ws,
                        int K, int dout) {
    int idx = blockIdx.x * blockDim.x + threadIdx.x;   // 256*128
    int n = idx >> 7, k = idx & 127;
    float v = 0.f;
    if (k < K) {
        if (n < 128) { if (n < dout) v = Wn[k * dout + n]; }
        else { int s = n - 128; if (s < dout) v = Ws[k * dout + s]; }
    }
    __nv_bfloat16 h, l;
    split_bf(v, h, l);
    g_bh[idx] = h;
    g_bl[idx] = l;
}

// ---------------- pipelined HMMA GEMM ----------------
// Per CTA: 128(m) x 128(n) tile, K=128 in 4 chunks of 32, 2-stage cp.async.
// blockIdx.y = 0: B rows [0,128) (Wn) -> Yn fp16;  = 1: B rows [128,256) -> Ys fp32.
// smem/stage: 4 planes (Ah,Al,Bh,Bl) x 128 rows x 80B = 40960B; 2 stages.
#define PITCH  80
#define PLANE  10240
#define STAGEB 40960
#define GEMM_SMEM 81920

__global__ void __launch_bounds__(256, 2)
k_gemm_pipe(const __nv_bfloat16* __restrict__ ah, const __nv_bfloat16* __restrict__ al,
            const __nv_bfloat16* __restrict__ bh, const __nv_bfloat16* __restrict__ bl,
            __half* __restrict__ Yn, float* __restrict__ Ys)
{
    extern __shared__ char smem[];
    const int tid = threadIdx.x;
    const int m0 = blockIdx.x * 128;
    const int n0 = blockIdx.y * 128;
    const uint32_t sb = smem_u32(smem);

    // ---- stage fill via cp.async (2 items/thread/plane) ----
    const int f_row = tid >> 2;          // 0..63 (+64 on second item)
    const int f_kc  = tid & 3;
    #define FILL(st, ks) do {                                                  \
        uint32_t sbase = sb + (st) * STAGEB;                                   \
        _Pragma("unroll")                                                      \
        for (int i = 0; i < 2; ++i) {                                          \
            int row = f_row + i * 64;                                          \
            uint32_t doff = row * PITCH + f_kc * 16;                           \
            size_t ga = (size_t)(m0 + row) * 128 + (ks) * 32 + f_kc * 8;       \
            size_t gb = (size_t)(n0 + row) * 128 + (ks) * 32 + f_kc * 8;       \
            cpa16(sbase + doff,             ah + ga);                          \
            cpa16(sbase + PLANE + doff,     al + ga);                          \
            cpa16(sbase + 2 * PLANE + doff, bh + gb);                          \
            cpa16(sbase + 3 * PLANE + doff, bl + gb);                          \
        }                                                                      \
    } while (0)

    FILL(0, 0); cp_commit();
    FILL(1, 1); cp_commit();

    const int wid = tid >> 5, lane = tid & 31;
    const int wm  = (wid & 1) * 64;      // warp m offset
    const int wn2 = (wid >> 1) * 32;     // warp n offset

    float acc[4][4][4];
    #pragma unroll
    for (int mf = 0; mf < 4; ++mf)
        #pragma unroll
        for (int nf = 0; nf < 4; ++nf)
            #pragma unroll
            for (int q = 0; q < 4; ++q) acc[mf][nf][q] = 0.f;

    const uint32_t aL = (uint32_t)(lane & 15) * PITCH + (lane >> 4) * 16;
    const uint32_t bL = (uint32_t)((lane & 7) + ((lane >> 4) << 3)) * PITCH
                        + ((lane >> 3) & 1) * 16;

    #pragma unroll
    for (int ks = 0; ks < 4; ++ks) {
        cp_wait<1>();
        __syncthreads();
        const uint32_t st = sb + (ks & 1) * STAGEB;
        #pragma unroll
        for (int kk = 0; kk < 2; ++kk) {
            const uint32_t kb = kk * 32;
            uint32_t Ah[4][4], Al[4][4];
            #pragma unroll
            for (int mf = 0; mf < 4; ++mf) {
                uint32_t base = st + (uint32_t)(wm + mf * 16) * PITCH + aL + kb;
                ldsm4(Ah[mf], base);
                ldsm4(Al[mf], base + PLANE);
            }
            #pragma unroll
            for (int nq = 0; nq < 2; ++nq) {
                uint32_t bbase = st + 2 * PLANE + (uint32_t)(wn2 + nq * 16) * PITCH + bL + kb;
                uint32_t Bh4[4], Bl4[4];
                ldsm4(Bh4, bbase);
                ldsm4(Bl4, bbase + PLANE);
                #pragma unroll
                for (int mf = 0; mf < 4; ++mf) {
                    float* c0 = acc[mf][2 * nq];
                    float* c1 = acc[mf][2 * nq + 1];
                    mma16816(c0, Ah[mf], Bh4[0], Bh4[1]);
                    mma16816(c0, Ah[mf], Bl4[0], Bl4[1]);
                    mma16816(c0, Al[mf], Bh4[0], Bh4[1]);
                    mma16816(c1, Ah[mf], Bh4[2], Bh4[3]);
                    mma16816(c1, Ah[mf], Bl4[2], Bl4[3]);
                    mma16816(c1, Al[mf], Bh4[2], Bh4[3]);
                }
            }
        }
        __syncthreads();
        if (ks + 2 < 4) FILL(ks & 1, ks + 2);
        cp_commit();                      // keep group counting uniform
    }

    // ---- epilogue ----
    const int gid = lane >> 2, tig = lane & 3;
    if (blockIdx.y == 0) {
        #pragma unroll
        for (int mf = 0; mf < 4; ++mf) {
            int r = m0 + wm + mf * 16 + gid;
            #pragma unroll
            for (int nf = 0; nf < 4; ++nf) {
                int col = wn2 + nf * 8 + tig * 2;
                *(__half2*)&Yn[(size_t)r * 128 + col] =
                    __floats2half2_rn(acc[mf][nf][0], acc[mf][nf][1]);
                *(__half2*)&Yn[(size_t)(r + 8) * 128 + col] =
                    __floats2half2_rn(acc[mf][nf][2], acc[mf][nf][3]);
            }
        }
    } else {
        #pragma unroll
        for (int mf = 0; mf < 4; ++mf) {
            int r = m0 + wm + mf * 16 + gid;
            #pragma unroll
            for (int nf = 0; nf < 4; ++nf) {
                int col = wn2 + nf * 8 + tig * 2;
                *(float2*)&Ys[(size_t)r * 128 + col] =
                    make_float2(acc[mf][nf][0], acc[mf][nf][1]);
                *(float2*)&Ys[(size_t)(r + 8) * 128 + col] =
                    make_float2(acc[mf][nf][2], acc[mf][nf][3]);
            }
        }
    }
}

// ---------------- fused aggregation + epilogue ----------------
// h = relu?( Ys[n,c] + invdeg[n] * sum_{s in N(n)} Yn[s,c] + b[c] )
template<int DOUT, int RELU, int OUTBF>
__global__ void k_agg(const __half* __restrict__ Yn, const float* __restrict__ Ys,
                      const float* __restrict__ bias,
                      __nv_bfloat16* __restrict__ oh, __nv_bfloat16* __restrict__ ol,
                      float* __restrict__ of)
{
    int warp = (int)((blockIdx.x * blockDim.x + threadIdx.x) >> 5);
    int lane = threadIdx.x & 31;
    if (warp >= N_NODES) return;
    int beg = g_rowptr[warp];
    int cnt = g_rowcnt[warp];
    const int NL = (DOUT + 3) >> 2;
    const bool act = lane < NL;
    const int c = lane * 4;

    float4 s = make_float4(0.f, 0.f, 0.f, 0.f);
    int j = 0;
    for (; j + 2 <= cnt; j += 2) {
        int s0 = g_csr[beg + j];
        int s1 = g_csr[beg + j + 1];
        if (act) {
            uint2 u0 = *(const uint2*)(Yn + (size_t)s0 * 128 + c);
            uint2 u1 = *(const uint2*)(Yn + (size_t)s1 * 128 + c);
            float2 a0 = __half22float2(*(__half2*)&u0.x);
            float2 a1 = __half22float2(*(__half2*)&u0.y);
            float2 b0 = __half22float2(*(__half2*)&u1.x);
            float2 b1 = __half22float2(*(__half2*)&u1.y);
            s.x += a0.x + b0.x; s.y += a0.y + b0.y;
            s.z += a1.x + b1.x; s.w += a1.y + b1.y;
        }
    }
    if (j < cnt) {
        int s0 = g_csr[beg + j];
        if (act) {
            uint2 u0 = *(const uint2*)(Yn + (size_t)s0 * 128 + c);
            float2 a0 = __half22float2(*(__half2*)&u0.x);
            float2 a1 = __half22float2(*(__half2*)&u0.y);
            s.x += a0.x; s.y += a0.y; s.z += a1.x; s.w += a1.y;
        }
    }

    float v[4] = { 0.f, 0.f, 0.f, 0.f };
    if (act) {
        float inv = g_invdeg[warp];
        const float* self = Ys + (size_t)warp * 128 + c;
        float sv[4] = { s.x, s.y, s.z, s.w };
        #pragma unroll
        for (int t = 0; t < 4; ++t) {
            int cc = c + t;
            if (cc < DOUT) {
                float x = self[t] + sv[t] * inv + bias[cc];
                v[t] = RELU ? fmaxf(x, 0.f) : x;
            }
        }
    }

    if (OUTBF) {
        if (act) {
            union { __nv_bfloat162 b2[2]; uint2 u; } uh, ul;
            #pragma unroll
            for (int t = 0; t < 2; ++t) {
                __nv_bfloat16 h0, l0, h1, l1;
                split_bf(v[2*t], h0, l0);
                split_bf(v[2*t+1], h1, l1);
                uh.b2[t] = __nv_bfloat162(h0, h1);
                ul.b2[t] = __nv_bfloat162(l0, l1);
            }
            *(uint2*)(oh + (size_t)warp * 128 + c) = uh.u;
            *(uint2*)(ol + (size_t)warp * 128 + c) = ul.u;
        }
    } else {
        if (act && c < 104)
            *(float4*)(of + (size_t)warp * 104 + c) = make_float4(v[0], v[1], v[2], v[3]);
    }
}

// ---------------- layer 4: tiny GEMM (N=10) + agg ----------------
__global__ void k_gemm4(const float* __restrict__ h3,
                        const float* __restrict__ ws4, const float* __restrict__ wn4,
                        float* __restrict__ hs4, float* __restrict__ hn4)
{
    __shared__ float sW[1030];
    int tid = threadIdx.x;
    for (int idx = tid; idx < 1030; idx += 256) {
        int k = idx / 10, cc = idx % 10;
        sW[idx] = (cc < 5) ? ws4[k * 5 + cc] : wn4[k * 5 + (cc - 5)];
    }
    __syncthreads();
    int node = blockIdx.x * 16 + (tid >> 4);
    int cc = tid & 15;
    if (node >= N_NODES || cc >= 10) return;
    const float* row = h3 + (size_t)node * 104;
    float acc = 0.f;
    #pragma unroll 4
    for (int k = 0; k < 103; ++k) acc += row[k] * sW[k * 10 + cc];
    if (cc < 5) hs4[node * 8 + cc] = acc;
    else        hn4[node * 8 + (cc - 5)] = acc;
}

__global__ void k_agg4(const float* __restrict__ hn4, const float* __restrict__ hs4,
                       const float* __restrict__ b4, float* __restrict__ h4)
{
    int n = blockIdx.x * blockDim.x + threadIdx.x;
    if (n >= N_NODES) return;
    int beg = g_rowptr[n], cnt = g_rowcnt[n];
    float a0 = 0.f, a1 = 0.f, a2 = 0.f, a3 = 0.f, a4 = 0.f;
    for (int j = 0; j < cnt; ++j) {
        const float* r = hn4 + (size_t)g_csr[beg + j] * 8;
        a0 += __ldg(r + 0); a1 += __ldg(r + 1); a2 += __ldg(r + 2);
        a3 += __ldg(r + 3); a4 += __ldg(r + 4);
    }
    float inv = g_invdeg[n];
    h4[n * 8 + 0] = hs4[n * 8 + 0] + inv * a0 + b4[0];
    h4[n * 8 + 1] = hs4[n * 8 + 1] + inv * a1 + b4[1];
    h4[n * 8 + 2] = hs4[n * 8 + 2] + inv * a2 + b4[2];
    h4[n * 8 + 3] = hs4[n * 8 + 3] + inv * a3 + b4[3];
    h4[n * 8 + 4] = hs4[n * 8 + 4] + inv * a4 + b4[4];
}

// ---------------- graph mean pooling ----------------
__global__ void k_pool(const float* __restrict__ h4, const int* __restrict__ gids) {
    int n = blockIdx.x * blockDim.x + threadIdx.x;
    if (n >= N_NODES) return;
    int g = gids[n];
    atomicAdd(&g_gcnt[g], 1);
    #pragma unroll
    for (int cc = 0; cc < 5; ++cc)
        atomicAdd(&g_pool[g * 5 + cc], h4[n * 8 + cc]);
}

__global__ void k_final(float* __restrict__ out) {
    int i = blockIdx.x * blockDim.x + threadIdx.x;
    if (i < N_GRAPHS * 5) {
        int g = i / 5;
        int c = g_gcnt[g];
        out[i] = g_pool[i] / (float)(c > 0 ? c : 1);
    }
}

// ---------------- launch ----------------
extern "C" void kernel_launch(void* const* d_in, const int* in_sizes, int n_in,
                              void* d_out, int out_size)
{
    const float* in_feat = (const float*)d_in[0];
    const int*   src     = (const int*)d_in[1];
    const int*   dst     = (const int*)d_in[2];
    const int*   gids    = (const int*)d_in[3];
    const float* ws[4] = { (const float*)d_in[4],  (const float*)d_in[7],
                           (const float*)d_in[10], (const float*)d_in[13] };
    const float* wn[4] = { (const float*)d_in[5],  (const float*)d_in[8],
                           (const float*)d_in[11], (const float*)d_in[14] };
    const float* bs[4] = { (const float*)d_in[6],  (const float*)d_in[9],
                           (const float*)d_in[12], (const float*)d_in[15] };

    __nv_bfloat16 *ah, *al, *bh, *bl;
    __half* yn;
    float *ys, *h3, *h4;
    cudaGetSymbolAddress((void**)&ah, g_ah);
    cudaGetSymbolAddress((void**)&al, g_al);
    cudaGetSymbolAddress((void**)&bh, g_bh);
    cudaGetSymbolAddress((void**)&bl, g_bl);
    cudaGetSymbolAddress((void**)&yn, g_yn);
    cudaGetSymbolAddress((void**)&ys, g_ys);
    cudaGetSymbolAddress((void**)&h3, g_h3);
    cudaGetSymbolAddress((void**)&h4, g_h4);
    float* hs4 = ys;                 // g_ys free after agg3
    float* hn4 = ys + 800000;

    cudaFuncSetAttribute(k_gemm_pipe, cudaFuncAttributeMaxDynamicSharedMemorySize, GEMM_SMEM);

    const int TB = 256;
    const dim3 gemmGrid(N_PAD / 128, 2);            // 782 x 2
    const int aggBlocks = (N_NODES + 7) / 8;        // warp per node

    k_zero<<<(N_NODES + TB - 1) / TB, TB>>>();                               // 0
    k_wconv<<<128, TB>>>(wn[0], ws[0], 128, 128);                            // 1
    k_conv_in<<<(N_PAD * 128) / TB, TB>>>(in_feat);                          // 2
    k_gemm_pipe<<<gemmGrid, TB, GEMM_SMEM>>>(ah, al, bh, bl, yn, ys);        // 3 (profiled)
    k_count<<<(N_EDGES + TB - 1) / TB, TB>>>(dst);                           // 4
    k_scan1<<<NB_SCAN, SCAN_B>>>();                                          // 5
    k_scan2<<<1, 128>>>();                                                   // 6
    k_scan3<<<NB_SCAN, SCAN_B>>>();                                          // 7
    k_fill<<<(N_EDGES + TB - 1) / TB, TB>>>(src, dst);                       // 8

    // layer 1 epilogue -> bf16 planes for layer 2
    k_agg<128, 1, 1><<<aggBlocks, TB>>>(yn, ys, bs[0], ah, al, nullptr);     // 9
    // layer 2
    k_wconv<<<128, TB>>>(wn[1], ws[1], 128, 118);                            // 10
    k_gemm_pipe<<<gemmGrid, TB, GEMM_SMEM>>>(ah, al, bh, bl, yn, ys);        // 11
    k_agg<118, 1, 1><<<aggBlocks, TB>>>(yn, ys, bs[1], ah, al, nullptr);     // 12
    // layer 3
    k_wconv<<<128, TB>>>(wn[2], ws[2], 118, 103);                            // 13
    k_gemm_pipe<<<gemmGrid, TB, GEMM_SMEM>>>(ah, al, bh, bl, yn, ys);        // 14
    k_agg<103, 1, 0><<<aggBlocks, TB>>>(yn, ys, bs[2], nullptr, nullptr, h3);// 15
    // layer 4 (SIMT, tiny)
    k_gemm4<<<(N_NODES + 15) / 16, TB>>>(h3, ws[3], wn[3], hs4, hn4);        // 16
    k_agg4<<<(N_NODES + TB - 1) / TB, TB>>>(hn4, hs4, bs[3], h4);            // 17
    // pooling
    k_pool<<<(N_NODES + TB - 1) / TB, TB>>>(h4, gids);                       // 18
    k_final<<<1, 512>>>((float*)d_out);                                      // 19
}

// round 6
// speedup vs baseline: 2.1314x; 1.0730x over previous
#include <cuda_runtime.h>
#include <cuda_bf16.h>
#include <cuda_fp16.h>
#include <cstdint>

#define N_NODES  100000
#define N_PAD    100096          // 782 * 128
#define N_EDGES  1600000
#define N_GRAPHS 100
#define SCAN_B   1024
#define NB_SCAN  98

// ---------------- scratch (static __device__ allocations only) ----------------
__device__ __nv_bfloat16 g_ah[N_PAD * 128];   // A hi plane (pitch 128)
__device__ __nv_bfloat16 g_al[N_PAD * 128];   // A lo plane
__device__ __nv_bfloat16 g_bh[256 * 128];     // B hi plane [n][k]
__device__ __nv_bfloat16 g_bl[256 * 128];     // B lo plane
__device__ __half g_yn[N_PAD * 128];          // neighbor-transform out (fp16, pitch 128)
__device__ float  g_ys[N_PAD * 128];          // self-transform out (fp32, pitch 128)
__device__ float  g_h3[N_NODES * 104];        // layer-3 activation (fp32, pitch 104)
__device__ float  g_h4[N_NODES * 8];          // final node features (pitch 8)
__device__ float g_invdeg[N_NODES];
__device__ int   g_rowcnt[N_NODES];
__device__ int   g_rowptr[N_NODES];
__device__ int   g_cursor[N_NODES];
__device__ int   g_csr[N_EDGES];
__device__ int   g_bsum[128];
__device__ int   g_boff[128];
__device__ float g_pool[N_GRAPHS * 5];
__device__ int   g_gcnt[N_GRAPHS];

// ---------------- PTX helpers ----------------
__device__ __forceinline__ uint32_t smem_u32(const void* p) {
    uint32_t a;
    asm("{ .reg .u64 t; cvta.to.shared.u64 t, %1; cvt.u32.u64 %0, t; }" : "=r"(a) : "l"(p));
    return a;
}
__device__ __forceinline__ void ldsm4(uint32_t* r, uint32_t addr) {
    asm volatile("ldmatrix.sync.aligned.m8n8.x4.shared.b16 {%0,%1,%2,%3}, [%4];"
                 : "=r"(r[0]), "=r"(r[1]), "=r"(r[2]), "=r"(r[3]) : "r"(addr));
}
__device__ __forceinline__ void mma16816(float* c, const uint32_t* a,
                                         uint32_t b0, uint32_t b1) {
    asm volatile(
        "mma.sync.aligned.m16n8k16.row.col.f32.bf16.bf16.f32 "
        "{%0,%1,%2,%3}, {%4,%5,%6,%7}, {%8,%9}, {%0,%1,%2,%3};"
        : "+f"(c[0]), "+f"(c[1]), "+f"(c[2]), "+f"(c[3])
        : "r"(a[0]), "r"(a[1]), "r"(a[2]), "r"(a[3]), "r"(b0), "r"(b1));
}
__device__ __forceinline__ void cpa16(uint32_t d, const void* g) {
    asm volatile("cp.async.cg.shared.global [%0], [%1], 16;" :: "r"(d), "l"(g));
}
__device__ __forceinline__ void cp_commit() {
    asm volatile("cp.async.commit_group;" ::: "memory");
}
template<int N> __device__ __forceinline__ void cp_wait() {
    asm volatile("cp.async.wait_group %0;" :: "n"(N) : "memory");
}

// ---------------- CSR build ----------------
__global__ void k_zero() {
    int i = blockIdx.x * blockDim.x + threadIdx.x;
    if (i < N_NODES) g_rowcnt[i] = 0;
    if (i < N_GRAPHS * 5) g_pool[i] = 0.f;
    if (i < N_GRAPHS) g_gcnt[i] = 0;
}

__global__ void k_count(const int* __restrict__ dst) {
    int e = blockIdx.x * blockDim.x + threadIdx.x;
    if (e < N_EDGES) atomicAdd(&g_rowcnt[dst[e]], 1);
}

__global__ void k_scan1() {
    __shared__ int s[SCAN_B];
    int tid = threadIdx.x;
    int gid = blockIdx.x * SCAN_B + tid;
    int v = (gid < N_NODES) ? g_rowcnt[gid] : 0;
    s[tid] = v;
    __syncthreads();
    for (int off = 1; off < SCAN_B; off <<= 1) {
        int t = (tid >= off) ? s[tid - off] : 0;
        __syncthreads();
        s[tid] += t;
        __syncthreads();
    }
    if (gid < N_NODES) g_rowptr[gid] = s[tid] - v;
    if (tid == SCAN_B - 1) g_bsum[blockIdx.x] = s[tid];
}

__global__ void k_scan2() {
    __shared__ int s[128];
    int t = threadIdx.x;
    int v = (t < NB_SCAN) ? g_bsum[t] : 0;
    s[t] = v;
    __syncthreads();
    for (int off = 1; off < 128; off <<= 1) {
        int x = (t >= off) ? s[t - off] : 0;
        __syncthreads();
        s[t] += x;
        __syncthreads();
    }
    if (t < NB_SCAN) g_boff[t] = s[t] - v;
}

__global__ void k_scan3() {
    int gid = blockIdx.x * SCAN_B + threadIdx.x;
    if (gid < N_NODES) {
        int rp = g_rowptr[gid] + g_boff[blockIdx.x];
        g_rowptr[gid] = rp;
        g_cursor[gid] = rp;
        int c = g_rowcnt[gid];
        g_invdeg[gid] = 1.0f / (float)(c > 0 ? c : 1);
    }
}

__global__ void k_fill(const int* __restrict__ src, const int* __restrict__ dst) {
    int e = blockIdx.x * blockDim.x + threadIdx.x;
    if (e < N_EDGES) {
        int pos = atomicAdd(&g_cursor[dst[e]], 1);
        g_csr[pos] = src[e];
    }
}

// ---------------- input / weight conversion to bf16 hi/lo ----------------
__device__ __forceinline__ void split_bf(float v, __nv_bfloat16& h, __nv_bfloat16& l) {
    h = __float2bfloat16(v);
    l = __float2bfloat16(v - __bfloat162float(h));
}

__global__ void k_conv_in(const float* __restrict__ x) {
    int idx = blockIdx.x * blockDim.x + threadIdx.x;   // N_PAD*128
    int n = idx >> 7;
    float v = (n < N_NODES) ? x[idx] : 0.f;
    __nv_bfloat16 h, l;
    split_bf(v, h, l);
    g_ah[idx] = h;
    g_al[idx] = l;
}

// B[n][k] = Wn[k][n] (n<128) | Ws[k][n-128], zero-padded
__global__ void k_wconv(const float* __restrict__ Wn, const float* __restrict__ Ws,
                        int K, int dout) {
    int idx = blockIdx.x * blockDim.x + threadIdx.x;   // 256*128
    int n = idx >> 7, k = idx & 127;
    float v = 0.f;
    if (k < K) {
        if (n < 128) { if (n < dout) v = Wn[k * dout + n]; }
        else { int s = n - 128; if (s < dout) v = Ws[k * dout + s]; }
    }
    __nv_bfloat16 h, l;
    split_bf(v, h, l);
    g_bh[idx] = h;
    g_bl[idx] = l;
}

// ---------------- pipelined HMMA GEMM ----------------
// Per CTA: 128(m) x 128(n) tile, K=128 in 4 chunks of 32, 2-stage cp.async.
// blockIdx.y = 0: B rows [0,128) (Wn) -> Yn fp16;  = 1: B rows [128,256) -> Ys fp32.
// Product phases issued product-major so same-accumulator MMA reuse distance = 16.
#define PITCH  80
#define PLANE  10240
#define STAGEB 40960
#define GEMM_SMEM 81920

__global__ void __launch_bounds__(256, 2)
k_gemm_pipe(const __nv_bfloat16* __restrict__ ah, const __nv_bfloat16* __restrict__ al,
            const __nv_bfloat16* __restrict__ bh, const __nv_bfloat16* __restrict__ bl,
            __half* __restrict__ Yn, float* __restrict__ Ys)
{
    extern __shared__ char smem[];
    const int tid = threadIdx.x;
    const int m0 = blockIdx.x * 128;
    const int n0 = blockIdx.y * 128;
    const uint32_t sb = smem_u32(smem);

    const int f_row = tid >> 2;
    const int f_kc  = tid & 3;
    #define FILL(st, ks) do {                                                  \
        uint32_t sbase = sb + (st) * STAGEB;                                   \
        _Pragma("unroll")                                                      \
        for (int i = 0; i < 2; ++i) {                                          \
            int row = f_row + i * 64;                                          \
            uint32_t doff = row * PITCH + f_kc * 16;                           \
            size_t ga = (size_t)(m0 + row) * 128 + (ks) * 32 + f_kc * 8;       \
            size_t gb = (size_t)(n0 + row) * 128 + (ks) * 32 + f_kc * 8;       \
            cpa16(sbase + doff,             ah + ga);                          \
            cpa16(sbase + PLANE + doff,     al + ga);                          \
            cpa16(sbase + 2 * PLANE + doff, bh + gb);                          \
            cpa16(sbase + 3 * PLANE + doff, bl + gb);                          \
        }                                                                      \
    } while (0)

    FILL(0, 0); cp_commit();
    FILL(1, 1); cp_commit();

    const int wid = tid >> 5, lane = tid & 31;
    const int wm  = (wid & 1) * 64;
    const int wn2 = (wid >> 1) * 32;

    float acc[4][4][4];
    #pragma unroll
    for (int mf = 0; mf < 4; ++mf)
        #pragma unroll
        for (int nf = 0; nf < 4; ++nf)
            #pragma unroll
            for (int q = 0; q < 4; ++q) acc[mf][nf][q] = 0.f;

    const uint32_t aL = (uint32_t)(lane & 15) * PITCH + (lane >> 4) * 16;
    const uint32_t bL = (uint32_t)((lane & 7) + ((lane >> 4) << 3)) * PITCH
                        + ((lane >> 3) & 1) * 16;

    #pragma unroll
    for (int ks = 0; ks < 4; ++ks) {
        cp_wait<1>();
        __syncthreads();
        const uint32_t st = sb + (ks & 1) * STAGEB;
        #pragma unroll
        for (int kk = 0; kk < 2; ++kk) {
            const uint32_t kb = kk * 32;
            uint32_t Ah[4][4], Al[4][4], Bh4[2][4], Bl4[2][4];
            #pragma unroll
            for (int mf = 0; mf < 4; ++mf) {
                uint32_t base = st + (uint32_t)(wm + mf * 16) * PITCH + aL + kb;
                ldsm4(Ah[mf], base);
                ldsm4(Al[mf], base + PLANE);
            }
            #pragma unroll
            for (int nq = 0; nq < 2; ++nq) {
                uint32_t bbase = st + 2 * PLANE + (uint32_t)(wn2 + nq * 16) * PITCH + bL + kb;
                ldsm4(Bh4[nq], bbase);
                ldsm4(Bl4[nq], bbase + PLANE);
            }
            // phase 1: Ah * Bh  (16 independent MMAs)
            #pragma unroll
            for (int nq = 0; nq < 2; ++nq)
                #pragma unroll
                for (int mf = 0; mf < 4; ++mf) {
                    mma16816(acc[mf][2 * nq],     Ah[mf], Bh4[nq][0], Bh4[nq][1]);
                    mma16816(acc[mf][2 * nq + 1], Ah[mf], Bh4[nq][2], Bh4[nq][3]);
                }
            // phase 2: Al * Bh
            #pragma unroll
            for (int nq = 0; nq < 2; ++nq)
                #pragma unroll
                for (int mf = 0; mf < 4; ++mf) {
                    mma16816(acc[mf][2 * nq],     Al[mf], Bh4[nq][0], Bh4[nq][1]);
                    mma16816(acc[mf][2 * nq + 1], Al[mf], Bh4[nq][2], Bh4[nq][3]);
                }
            // phase 3: Ah * Bl
            #pragma unroll
            for (int nq = 0; nq < 2; ++nq)
                #pragma unroll
                for (int mf = 0; mf < 4; ++mf) {
                    mma16816(acc[mf][2 * nq],     Ah[mf], Bl4[nq][0], Bl4[nq][1]);
                    mma16816(acc[mf][2 * nq + 1], Ah[mf], Bl4[nq][2], Bl4[nq][3]);
                }
        }
        __syncthreads();
        if (ks + 2 < 4) FILL(ks & 1, ks + 2);
        cp_commit();
    }

    // ---- epilogue ----
    const int gid = lane >> 2, tig = lane & 3;
    if (blockIdx.y == 0) {
        #pragma unroll
        for (int mf = 0; mf < 4; ++mf) {
            int r = m0 + wm + mf * 16 + gid;
            #pragma unroll
            for (int nf = 0; nf < 4; ++nf) {
                int col = wn2 + nf * 8 + tig * 2;
                *(__half2*)&Yn[(size_t)r * 128 + col] =
                    __floats2half2_rn(acc[mf][nf][0], acc[mf][nf][1]);
                *(__half2*)&Yn[(size_t)(r + 8) * 128 + col] =
                    __floats2half2_rn(acc[mf][nf][2], acc[mf][nf][3]);
            }
        }
    } else {
        #pragma unroll
        for (int mf = 0; mf < 4; ++mf) {
            int r = m0 + wm + mf * 16 + gid;
            #pragma unroll
            for (int nf = 0; nf < 4; ++nf) {
                int col = wn2 + nf * 8 + tig * 2;
                *(float2*)&Ys[(size_t)r * 128 + col] =
                    make_float2(acc[mf][nf][0], acc[mf][nf][1]);
                *(float2*)&Ys[(size_t)(r + 8) * 128 + col] =
                    make_float2(acc[mf][nf][2], acc[mf][nf][3]);
            }
        }
    }
}

// ---------------- fused aggregation + epilogue ----------------
// Half-warp (16 lanes) per node; each lane covers 8 contiguous cols via uint4.
// h = relu?( Ys[n,c] + invdeg[n] * sum_{s in N(n)} Yn[s,c] + b[c] ); cols >= DOUT -> 0.
template<int DOUT, int RELU, int OUTBF>
__global__ void k_agg(const __half* __restrict__ Yn, const float* __restrict__ Ys,
                      const float* __restrict__ bias,
                      __nv_bfloat16* __restrict__ oh, __nv_bfloat16* __restrict__ ol,
                      float* __restrict__ of)
{
    int node = (int)((blockIdx.x * blockDim.x + threadIdx.x) >> 4);
    int l = threadIdx.x & 15;
    if (node >= N_NODES) return;
    int beg = g_rowptr[node];
    int cnt = g_rowcnt[node];
    const int c = l * 8;

    float s[8];
    #pragma unroll
    for (int t = 0; t < 8; ++t) s[t] = 0.f;

    int j = 0;
    for (; j + 2 <= cnt; j += 2) {
        int s0 = g_csr[beg + j];
        int s1 = g_csr[beg + j + 1];
        uint4 u0 = *(const uint4*)(Yn + (size_t)s0 * 128 + c);
        uint4 u1 = *(const uint4*)(Yn + (size_t)s1 * 128 + c);
        const __half2* h0 = (const __half2*)&u0;
        const __half2* h1 = (const __half2*)&u1;
        #pragma unroll
        for (int q = 0; q < 4; ++q) {
            float2 f0 = __half22float2(h0[q]);
            float2 f1 = __half22float2(h1[q]);
            s[2 * q]     += f0.x + f1.x;
            s[2 * q + 1] += f0.y + f1.y;
        }
    }
    if (j < cnt) {
        int s0 = g_csr[beg + j];
        uint4 u0 = *(const uint4*)(Yn + (size_t)s0 * 128 + c);
        const __half2* h0 = (const __half2*)&u0;
        #pragma unroll
        for (int q = 0; q < 4; ++q) {
            float2 f0 = __half22float2(h0[q]);
            s[2 * q]     += f0.x;
            s[2 * q + 1] += f0.y;
        }
    }

    float inv = g_invdeg[node];
    float4 self0 = *(const float4*)(Ys + (size_t)node * 128 + c);
    float4 self1 = *(const float4*)(Ys + (size_t)node * 128 + c + 4);
    float selfv[8] = { self0.x, self0.y, self0.z, self0.w,
                       self1.x, self1.y, self1.z, self1.w };
    float v[8];
    #pragma unroll
    for (int t = 0; t < 8; ++t) {
        int cc = c + t;
        if (cc < DOUT) {
            float x = selfv[t] + s[t] * inv + bias[cc];
            v[t] = RELU ? fmaxf(x, 0.f) : x;
        } else {
            v[t] = 0.f;
        }
    }

    if (OUTBF) {
        union { __nv_bfloat162 b2[4]; uint4 u; } uh, ul;
        #pragma unroll
        for (int q = 0; q < 4; ++q) {
            __nv_bfloat16 h0, l0, h1, l1;
            split_bf(v[2 * q], h0, l0);
            split_bf(v[2 * q + 1], h1, l1);
            uh.b2[q] = __nv_bfloat162(h0, h1);
            ul.b2[q] = __nv_bfloat162(l0, l1);
        }
        *(uint4*)(oh + (size_t)node * 128 + c) = uh.u;
        *(uint4*)(ol + (size_t)node * 128 + c) = ul.u;
    } else {
        if (c < 104) {   // pitch 104: lanes 0..12 cover cols 0..103 exactly
            *(float4*)(of + (size_t)node * 104 + c) =
                make_float4(v[0], v[1], v[2], v[3]);
            *(float4*)(of + (size_t)node * 104 + c + 4) =
                make_float4(v[4], v[5], v[6], v[7]);
        }
    }
}

// ---------------- layer 4: tiny GEMM (N=10) + agg ----------------
// h3 col 103 is exact 0 (agg zero-pads), sW k=103 row is 0 -> float4 over 104 safe.
__global__ void k_gemm4(const float* __restrict__ h3,
                        const float* __restrict__ ws4, const float* __restrict__ wn4,
                        float* __restrict__ hs4, float* __restrict__ hn4)
{
    __shared__ float sW[1040];           // [k 0..103][c 0..9]
    int tid = threadIdx.x;
    for (int idx = tid; idx < 1040; idx += 256) {
        int k = idx / 10, cc = idx % 10;
        sW[idx] = (k < 103) ? ((cc < 5) ? ws4[k * 5 + cc] : wn4[k * 5 + (cc - 5)]) : 0.f;
    }
    __syncthreads();
    int node = blockIdx.x * 16 + (tid >> 4);
    int cc = tid & 15;
    if (node >= N_NODES || cc >= 10) return;
    const float4* row = (const float4*)(h3 + (size_t)node * 104);
    float acc = 0.f;
    #pragma unroll 13
    for (int kc = 0; kc < 26; ++kc) {
        float4 r = __ldg(row + kc);
        int kb = kc * 40;                // 4k * 10
        acc += r.x * sW[kb + cc] + r.y * sW[kb + 10 + cc]
             + r.z * sW[kb + 20 + cc] + r.w * sW[kb + 30 + cc];
    }
    if (cc < 5) hs4[node * 8 + cc] = acc;
    else        hn4[node * 8 + (cc - 5)] = acc;
}

__global__ void k_agg4(const float* __restrict__ hn4, const float* __restrict__ hs4,
                       const float* __restrict__ b4, float* __restrict__ h4)
{
    int n = blockIdx.x * blockDim.x + threadIdx.x;
    if (n >= N_NODES) return;
    int beg = g_rowptr[n], cnt = g_rowcnt[n];
    float a0 = 0.f, a1 = 0.f, a2 = 0.f, a3 = 0.f, a4 = 0.f;
    for (int j = 0; j < cnt; ++j) {
        const float* r = hn4 + (size_t)g_csr[beg + j] * 8;
        a0 += __ldg(r + 0); a1 += __ldg(r + 1); a2 += __ldg(r + 2);
        a3 += __ldg(r + 3); a4 += __ldg(r + 4);
    }
    float inv = g_invdeg[n];
    h4[n * 8 + 0] = hs4[n * 8 + 0] + inv * a0 + b4[0];
    h4[n * 8 + 1] = hs4[n * 8 + 1] + inv * a1 + b4[1];
    h4[n * 8 + 2] = hs4[n * 8 + 2] + inv * a2 + b4[2];
    h4[n * 8 + 3] = hs4[n * 8 + 3] + inv * a3 + b4[3];
    h4[n * 8 + 4] = hs4[n * 8 + 4] + inv * a4 + b4[4];
}

// ---------------- graph mean pooling ----------------
__global__ void k_pool(const float* __restrict__ h4, const int* __restrict__ gids) {
    int n = blockIdx.x * blockDim.x + threadIdx.x;
    if (n >= N_NODES) return;
    int g = gids[n];
    atomicAdd(&g_gcnt[g], 1);
    #pragma unroll
    for (int cc = 0; cc < 5; ++cc)
        atomicAdd(&g_pool[g * 5 + cc], h4[n * 8 + cc]);
}

__global__ void k_final(float* __restrict__ out) {
    int i = blockIdx.x * blockDim.x + threadIdx.x;
    if (i < N_GRAPHS * 5) {
        int g = i / 5;
        int c = g_gcnt[g];
        out[i] = g_pool[i] / (float)(c > 0 ? c : 1);
    }
}

// ---------------- launch ----------------
extern "C" void kernel_launch(void* const* d_in, const int* in_sizes, int n_in,
                              void* d_out, int out_size)
{
    const float* in_feat = (const float*)d_in[0];
    const int*   src     = (const int*)d_in[1];
    const int*   dst     = (const int*)d_in[2];
    const int*   gids    = (const int*)d_in[3];
    const float* ws[4] = { (const float*)d_in[4],  (const float*)d_in[7],
                           (const float*)d_in[10], (const float*)d_in[13] };
    const float* wn[4] = { (const float*)d_in[5],  (const float*)d_in[8],
                           (const float*)d_in[11], (const float*)d_in[14] };
    const float* bs[4] = { (const float*)d_in[6],  (const float*)d_in[9],
                           (const float*)d_in[12], (const float*)d_in[15] };

    __nv_bfloat16 *ah, *al, *bh, *bl;
    __half* yn;
    float *ys, *h3, *h4;
    cudaGetSymbolAddress((void**)&ah, g_ah);
    cudaGetSymbolAddress((void**)&al, g_al);
    cudaGetSymbolAddress((void**)&bh, g_bh);
    cudaGetSymbolAddress((void**)&bl, g_bl);
    cudaGetSymbolAddress((void**)&yn, g_yn);
    cudaGetSymbolAddress((void**)&ys, g_ys);
    cudaGetSymbolAddress((void**)&h3, g_h3);
    cudaGetSymbolAddress((void**)&h4, g_h4);
    float* hs4 = ys;                 // g_ys free after agg3
    float* hn4 = ys + 800000;

    cudaFuncSetAttribute(k_gemm_pipe, cudaFuncAttributeMaxDynamicSharedMemorySize, GEMM_SMEM);

    const int TB = 256;
    const dim3 gemmGrid(N_PAD / 128, 2);            // 782 x 2
    const int aggBlocks = (N_NODES * 16 + TB - 1) / TB;   // half-warp per node

    k_zero<<<(N_NODES + TB - 1) / TB, TB>>>();                               // 0
    k_wconv<<<128, TB>>>(wn[0], ws[0], 128, 128);                            // 1
    k_conv_in<<<(N_PAD * 128) / TB, TB>>>(in_feat);                          // 2
    k_gemm_pipe<<<gemmGrid, TB, GEMM_SMEM>>>(ah, al, bh, bl, yn, ys);        // 3 (profiled)
    k_count<<<(N_EDGES + TB - 1) / TB, TB>>>(dst);                           // 4
    k_scan1<<<NB_SCAN, SCAN_B>>>();                                          // 5
    k_scan2<<<1, 128>>>();                                                   // 6
    k_scan3<<<NB_SCAN, SCAN_B>>>();                                          // 7
    k_fill<<<(N_EDGES + TB - 1) / TB, TB>>>(src, dst);                       // 8

    // layer 1 epilogue -> bf16 planes for layer 2
    k_agg<128, 1, 1><<<aggBlocks, TB>>>(yn, ys, bs[0], ah, al, nullptr);     // 9
    // layer 2
    k_wconv<<<128, TB>>>(wn[1], ws[1], 128, 118);                            // 10
    k_gemm_pipe<<<gemmGrid, TB, GEMM_SMEM>>>(ah, al, bh, bl, yn, ys);        // 11
    k_agg<118, 1, 1><<<aggBlocks, TB>>>(yn, ys, bs[1], ah, al, nullptr);     // 12
    // layer 3
    k_wconv<<<128, TB>>>(wn[2], ws[2], 118, 103);                            // 13
    k_gemm_pipe<<<gemmGrid, TB, GEMM_SMEM>>>(ah, al, bh, bl, yn, ys);        // 14
    k_agg<103, 1, 0><<<aggBlocks, TB>>>(yn, ys, bs[2], nullptr, nullptr, h3);// 15
    // layer 4 (SIMT, tiny)
    k_gemm4<<<(N_NODES + 15) / 16, TB>>>(h3, ws[3], wn[3], hs4, hn4);        // 16
    k_agg4<<<(N_NODES + TB - 1) / TB, TB>>>(hn4, hs4, bs[3], h4);            // 17
    // pooling
    k_pool<<<(N_NODES + TB - 1) / TB, TB>>>(h4, gids);                       // 18
    k_final<<<1, 512>>>((float*)d_out);                                      // 19
}